// round 3
// baseline (speedup 1.0000x reference)
#include <cuda_runtime.h>
#include <cstdint>

#define BATCH 64
#define SEQ   1024
#define IDIM  256
#define HDIM  512
#define ODIM  128
#define G4    2048

// ---------------- device scratch ----------------
__device__ float g_xr[(size_t)BATCH * SEQ * IDIM];     // relu(x)
__device__ float g_xp[(size_t)SEQ * BATCH * G4];       // forward input projection [t*64+b][4H]
__device__ float g_h[2][BATCH * HDIM];                 // double-buffered hidden state
__device__ float g_last[BATCH * 2 * HDIM];
__device__ unsigned long long g_bar;

typedef unsigned long long ull;

__device__ __forceinline__ void ffma2(ull &acc, ull a, ull b) {
    asm("fma.rn.f32x2 %0, %1, %2, %0;" : "+l"(acc) : "l"(a), "l"(b));
}
__device__ __forceinline__ float2 unpack2(ull v) {
    float2 f; asm("mov.b64 {%0, %1}, %2;" : "=f"(f.x), "=f"(f.y) : "l"(v)); return f;
}
__device__ __forceinline__ ull dup2(float a) {
    ull r; asm("mov.b64 %0, {%1, %1};" : "=l"(r) : "f"(a)); return r;
}
__device__ __forceinline__ float sigf(float v) { return 1.0f / (1.0f + expf(-v)); }

// ================================================================
// Kernel 0: xr = relu(x)
// ================================================================
__global__ void __launch_bounds__(256) relu_kernel(const float* __restrict__ x)
{
    const size_t n = (size_t)BATCH * SEQ * IDIM / 4;
    const float4* xin = (const float4*)x;
    float4* xo = (float4*)g_xr;
    for (size_t u = (size_t)blockIdx.x * blockDim.x + threadIdx.x; u < n;
         u += (size_t)gridDim.x * blockDim.x) {
        float4 v = __ldcs(xin + u);
        v.x = fmaxf(v.x, 0.f); v.y = fmaxf(v.y, 0.f);
        v.z = fmaxf(v.z, 0.f); v.w = fmaxf(v.w, 0.f);
        xo[u] = v;
    }
}

// ================================================================
// Kernel 1: xp = xr @ W_ih_f^T + b_f   (M=65536, N=2048, K=256)
// 128x64x32 tiles, double-buffered, 8x4 microtile with f32x2.
// M row = t*64 + b; BM=128 covers 2 time steps.
// ================================================================
#define BM 128
#define BN 64
#define BK 32
#define ALD 132
#define BLD 68
#define GEMM_SMEM ((2*BK*ALD + 2*BK*BLD) * 4)

__global__ void __launch_bounds__(256, 2) gemm_xp_kernel(
    const float* __restrict__ Wih, const float* __restrict__ bias)
{
    extern __shared__ float smg[];
    float* As = smg;                 // [2][BK][ALD]   [k][m]
    float* Bs = smg + 2 * BK * ALD;  // [2][BK][BLD]   [k][n]

    const int tid = threadIdx.x;
    const int n0  = blockIdx.x * BN;
    const int t0  = blockIdx.y * 2;
    const int tx  = tid & 15;        // n group (4 cols)
    const int ty  = tid >> 4;        // m group (8 rows)

    const int mA = tid >> 3, kqA = tid & 7;
    const float* aptr[4];
#pragma unroll
    for (int i = 0; i < 4; i++) {
        int m = mA + i * 32;
        aptr[i] = g_xr + ((size_t)(m & 63) * SEQ + t0 + (m >> 6)) * IDIM + kqA * 4;
    }
    const int nB = tid >> 3, kqB = tid & 7;
    const float* bptr[2];
#pragma unroll
    for (int i = 0; i < 2; i++)
        bptr[i] = Wih + (size_t)(n0 + nB + i * 32) * IDIM + kqB * 4;

    ull acc[8][2];
#pragma unroll
    for (int i = 0; i < 8; i++) { acc[i][0] = 0; acc[i][1] = 0; }

    float4 ra[4], rb[2];
#pragma unroll
    for (int i = 0; i < 4; i++) ra[i] = *(const float4*)(aptr[i]);
#pragma unroll
    for (int i = 0; i < 2; i++) rb[i] = *(const float4*)(bptr[i]);

#define STSAB(BUF) do{                                                     \
    float* ab = As + (BUF) * BK * ALD;                                     \
    _Pragma("unroll") for (int i = 0; i < 4; i++) {                        \
        int m = mA + i * 32;                                               \
        ab[(kqA*4+0)*ALD + m] = ra[i].x; ab[(kqA*4+1)*ALD + m] = ra[i].y;  \
        ab[(kqA*4+2)*ALD + m] = ra[i].z; ab[(kqA*4+3)*ALD + m] = ra[i].w; }\
    float* bb = Bs + (BUF) * BK * BLD;                                     \
    _Pragma("unroll") for (int i = 0; i < 2; i++) {                        \
        int n = nB + i * 32;                                               \
        bb[(kqB*4+0)*BLD + n] = rb[i].x; bb[(kqB*4+1)*BLD + n] = rb[i].y;  \
        bb[(kqB*4+2)*BLD + n] = rb[i].z; bb[(kqB*4+3)*BLD + n] = rb[i].w; }\
}while(0)

    STSAB(0);
    __syncthreads();

    int buf = 0;
#pragma unroll 1
    for (int it = 0; it < 8; it++) {
        if (it < 7) {
#pragma unroll
            for (int i = 0; i < 4; i++) ra[i] = *(const float4*)(aptr[i] + (it + 1) * BK);
#pragma unroll
            for (int i = 0; i < 2; i++) rb[i] = *(const float4*)(bptr[i] + (it + 1) * BK);
        }
        {
            const float* ab = As + buf * BK * ALD + ty * 8;
            const float* bb = Bs + buf * BK * BLD + tx * 4;
#pragma unroll
            for (int k = 0; k < BK; k++) {
                float4 a0 = *(const float4*)(ab + k * ALD);
                float4 a1 = *(const float4*)(ab + k * ALD + 4);
                ulonglong2 bq = *(const ulonglong2*)(bb + k * BLD);
                ull ad;
                ad = dup2(a0.x); ffma2(acc[0][0], ad, bq.x); ffma2(acc[0][1], ad, bq.y);
                ad = dup2(a0.y); ffma2(acc[1][0], ad, bq.x); ffma2(acc[1][1], ad, bq.y);
                ad = dup2(a0.z); ffma2(acc[2][0], ad, bq.x); ffma2(acc[2][1], ad, bq.y);
                ad = dup2(a0.w); ffma2(acc[3][0], ad, bq.x); ffma2(acc[3][1], ad, bq.y);
                ad = dup2(a1.x); ffma2(acc[4][0], ad, bq.x); ffma2(acc[4][1], ad, bq.y);
                ad = dup2(a1.y); ffma2(acc[5][0], ad, bq.x); ffma2(acc[5][1], ad, bq.y);
                ad = dup2(a1.z); ffma2(acc[6][0], ad, bq.x); ffma2(acc[6][1], ad, bq.y);
                ad = dup2(a1.w); ffma2(acc[7][0], ad, bq.x); ffma2(acc[7][1], ad, bq.y);
            }
        }
        if (it < 7) {
            STSAB(buf ^ 1);
            __syncthreads();
            buf ^= 1;
        }
    }

    const int ncol = n0 + tx * 4;
    float4 bv = *(const float4*)(bias + ncol);
#pragma unroll
    for (int i = 0; i < 8; i++) {
        int m = ty * 8 + i;
        int row = (t0 + (m >> 6)) * BATCH + (m & 63);
        float2 p0 = unpack2(acc[i][0]);
        float2 p1 = unpack2(acc[i][1]);
        float4 o;
        o.x = p0.x + bv.x; o.y = p0.y + bv.y;
        o.z = p1.x + bv.z; o.w = p1.y + bv.w;
        *(float4*)(g_xp + (size_t)row * G4 + ncol) = o;
    }
}

// ================================================================
// Kernel 2: backward-direction last hidden state (single step from 0).
// ================================================================
__global__ void __launch_bounds__(256) bwd_last_kernel(
    const float* __restrict__ Wb, const float* __restrict__ bb)
{
    __shared__ float xs[IDIM];
    const int b = blockIdx.x, tid = threadIdx.x;
    xs[tid] = g_xr[((size_t)b * SEQ + (SEQ - 1)) * IDIM + tid];
    __syncthreads();

    const int j = blockIdx.y * 256 + tid;
    const int cols[3] = { j, 2 * HDIM + j, 3 * HDIM + j };    // i, g, o
    float acc[3] = { bb[cols[0]], bb[cols[1]], bb[cols[2]] };
#pragma unroll
    for (int gi = 0; gi < 3; gi++) {
        const float4* wp = (const float4*)(Wb + (size_t)cols[gi] * IDIM);
        float s = 0.f;
#pragma unroll 8
        for (int k4 = 0; k4 < IDIM / 4; k4++) {
            float4 w = __ldg(wp + k4);
            float4 xv = *(const float4*)&xs[k4 * 4];
            s += w.x * xv.x + w.y * xv.y + w.z * xv.z + w.w * xv.w;
        }
        acc[gi] += s;
    }
    float cst = sigf(acc[0]) * tanhf(acc[1]);
    float h   = sigf(acc[2]) * tanhf(cst);
    g_last[b * (2 * HDIM) + HDIM + j] = h;
}

// ================================================================
// Kernel 3: persistent forward LSTM scan, K-chunk pipelined.
// 128 blocks x 256 threads; block owns 16 gate cols (4 H-cols).
// Per thread: 2 batches x 2 cols; xp prefetched before barrier.
// ================================================================
#define SCAN_BLOCKS 128
#define WPAD 516
#define HS_LD 132
#define SCAN_SMEM ((16*WPAD + 2*64*HS_LD + 64*17) * 4)

__device__ __forceinline__ void gridbar() {
    __syncthreads();
    if (threadIdx.x == 0) {
        __threadfence();
        ull old = atomicAdd(&g_bar, 1ull);
        ull target = (old / SCAN_BLOCKS + 1) * SCAN_BLOCKS;
        ull v;
        do {
            asm volatile("ld.acquire.gpu.global.u64 %0, [%1];"
                         : "=l"(v) : "l"(&g_bar) : "memory");
        } while (v < target);
    }
    __syncthreads();
}

__global__ void __launch_bounds__(256, 1) lstm_scan_kernel(const float* __restrict__ Whh)
{
    extern __shared__ float sm[];
    float* ws = sm;                        // [16][WPAD]   W_hh slice [col][k]
    float* hs = sm + 16 * WPAD;            // [2][64][HS_LD]  h chunk buffers
    float* gs = hs + 2 * 64 * HS_LD;       // [64][17]     gate preacts

    const int tid = threadIdx.x;
    const int j0  = blockIdx.x * 4;

    // one-time W_hh slice load
    for (int u = tid; u < 16 * HDIM; u += 256) {
        int cc = u >> 9, k = u & (HDIM - 1);
        int gate = cc >> 2, jl = cc & 3;
        ws[cc * WPAD + k] = Whh[(size_t)(gate * HDIM + j0 + jl) * HDIM + k];
    }

    // compute role: 2 batches x 2 cols
    const int cp = tid & 7, bp = tid >> 3;
    const int lc0 = cp * 2, lc1 = cp * 2 + 1;
    const int b0 = bp * 2,  b1 = bp * 2 + 1;
    const float* w0 = ws + lc0 * WPAD;
    const float* w1 = ws + lc1 * WPAD;
    const int col0 = (lc0 >> 2) * HDIM + j0 + (lc0 & 3);
    const int col1 = (lc1 >> 2) * HDIM + j0 + (lc1 & 3);
    const size_t tstride = (size_t)BATCH * G4;
    const float* xp00 = g_xp + (size_t)b0 * G4 + col0;
    const float* xp01 = g_xp + (size_t)b0 * G4 + col1;
    const float* xp10 = g_xp + (size_t)b1 * G4 + col0;
    const float* xp11 = g_xp + (size_t)b1 * G4 + col1;

    // update role
    const int ub = tid >> 2, ujl = tid & 3;
    float cstate = 0.f;
    float* hout0 = &g_h[0][ub * HDIM + j0 + ujl];
    float* hout1 = &g_h[1][ub * HDIM + j0 + ujl];

    // staging role: b_i = sb + i*8, kq = skq (f4 units)
    const int sb = tid >> 5, skq = tid & 31;

    float xv00 = __ldcs(xp00), xv01 = __ldcs(xp01);
    float xv10 = __ldcs(xp10), xv11 = __ldcs(xp11);
    __syncthreads();   // ws ready

    // ---- t = 0: h=0 -> gates = xp ----
    gs[b0 * 17 + lc0] = xv00; gs[b0 * 17 + lc1] = xv01;
    gs[b1 * 17 + lc0] = xv10; gs[b1 * 17 + lc1] = xv11;
    __syncthreads();
    {
        float gi = gs[ub * 17 + 0 + ujl], gf = gs[ub * 17 + 4 + ujl];
        float gg = gs[ub * 17 + 8 + ujl], go = gs[ub * 17 + 12 + ujl];
        float i_ = sigf(gi), f_ = sigf(gf), gv = tanhf(gg), o_ = sigf(go);
        cstate = fmaf(f_, cstate, i_ * gv);
        float h = o_ * tanhf(cstate);
        __stcg(hout1, h);
    }
    xv00 = __ldcs(xp00 + tstride); xv01 = __ldcs(xp01 + tstride);
    xv10 = __ldcs(xp10 + tstride); xv11 = __ldcs(xp11 + tstride);
    gridbar();

#define LOADR(CH) do{                                                          \
    const float4* p = src + (size_t)(CH) * 32 + skq;                           \
    R[0]=__ldcg(p+(sb+ 0)*128); R[1]=__ldcg(p+(sb+ 8)*128);                    \
    R[2]=__ldcg(p+(sb+16)*128); R[3]=__ldcg(p+(sb+24)*128);                    \
    R[4]=__ldcg(p+(sb+32)*128); R[5]=__ldcg(p+(sb+40)*128);                    \
    R[6]=__ldcg(p+(sb+48)*128); R[7]=__ldcg(p+(sb+56)*128);                    \
}while(0)

#define STSR(BUF) do{                                                          \
    float* d = hs + (BUF) * 64 * HS_LD + skq * 4;                              \
    *(float4*)(d+(sb+ 0)*HS_LD)=R[0]; *(float4*)(d+(sb+ 8)*HS_LD)=R[1];        \
    *(float4*)(d+(sb+16)*HS_LD)=R[2]; *(float4*)(d+(sb+24)*HS_LD)=R[3];        \
    *(float4*)(d+(sb+32)*HS_LD)=R[4]; *(float4*)(d+(sb+40)*HS_LD)=R[5];        \
    *(float4*)(d+(sb+48)*HS_LD)=R[6]; *(float4*)(d+(sb+56)*HS_LD)=R[7];        \
}while(0)

#define DOTS(BUF,CH) do{                                                       \
    const float* hb0 = hs + (BUF) * 64 * HS_LD + b0 * HS_LD;                   \
    const float* hb1 = hs + (BUF) * 64 * HS_LD + b1 * HS_LD;                   \
    const float* wa = w0 + (CH) * 128;                                         \
    const float* wb = w1 + (CH) * 128;                                         \
    _Pragma("unroll 8")                                                        \
    for (int kk = 0; kk < 128; kk += 4) {                                      \
        ulonglong2 W0 = *(const ulonglong2*)(wa + kk);                         \
        ulonglong2 W1 = *(const ulonglong2*)(wb + kk);                         \
        ulonglong2 H0 = *(const ulonglong2*)(hb0 + kk);                        \
        ulonglong2 H1 = *(const ulonglong2*)(hb1 + kk);                        \
        ffma2(a000, H0.x, W0.x); ffma2(a001, H0.y, W0.y);                      \
        ffma2(a010, H0.x, W1.x); ffma2(a011, H0.y, W1.y);                      \
        ffma2(a100, H1.x, W0.x); ffma2(a101, H1.y, W0.y);                      \
        ffma2(a110, H1.x, W1.x); ffma2(a111, H1.y, W1.y);                      \
    }                                                                          \
}while(0)

#pragma unroll 1
    for (int t = 1; t < SEQ; t++) {
        const float4* src = (const float4*)g_h[t & 1];
        float* hdst = (t & 1) ? hout0 : hout1;
        float4 R[8];
        ull a000=0,a001=0,a010=0,a011=0,a100=0,a101=0,a110=0,a111=0;

        LOADR(0);
        STSR(0); __syncthreads();
        LOADR(1);
        DOTS(0, 0);
        __syncthreads(); STSR(1); __syncthreads();
        LOADR(2);
        DOTS(1, 1);
        __syncthreads(); STSR(0); __syncthreads();
        LOADR(3);
        DOTS(0, 2);
        __syncthreads(); STSR(1); __syncthreads();
        DOTS(1, 3);

        {
            float2 p; float s00, s01, s10, s11;
            p = unpack2(a000); s00 = p.x + p.y; p = unpack2(a001); s00 += p.x + p.y;
            p = unpack2(a010); s01 = p.x + p.y; p = unpack2(a011); s01 += p.x + p.y;
            p = unpack2(a100); s10 = p.x + p.y; p = unpack2(a101); s10 += p.x + p.y;
            p = unpack2(a110); s11 = p.x + p.y; p = unpack2(a111); s11 += p.x + p.y;
            gs[b0 * 17 + lc0] = s00 + xv00; gs[b0 * 17 + lc1] = s01 + xv01;
            gs[b1 * 17 + lc0] = s10 + xv10; gs[b1 * 17 + lc1] = s11 + xv11;
        }
        __syncthreads();

        {
            float gi = gs[ub * 17 + 0 + ujl], gf = gs[ub * 17 + 4 + ujl];
            float gg = gs[ub * 17 + 8 + ujl], go = gs[ub * 17 + 12 + ujl];
            float i_ = sigf(gi), f_ = sigf(gf), gv = tanhf(gg), o_ = sigf(go);
            cstate = fmaf(f_, cstate, i_ * gv);
            float h = o_ * tanhf(cstate);
            __stcg(hdst, h);
            if (t == SEQ - 1)
                g_last[ub * (2 * HDIM) + j0 + ujl] = h;
        }

        if (t < SEQ - 1) {
            const size_t off = tstride * (size_t)(t + 1);
            xv00 = __ldcs(xp00 + off); xv01 = __ldcs(xp01 + off);
            xv10 = __ldcs(xp10 + off); xv11 = __ldcs(xp11 + off);
            gridbar();
        }
    }
}

// ================================================================
// Kernel 4: final FC. 64 blocks x 512 threads, 4 threads/output.
// ================================================================
__global__ void __launch_bounds__(512) fc_kernel(
    const float* __restrict__ Wfc, const float* __restrict__ bfc,
    float* __restrict__ out)
{
    __shared__ float ls[2 * HDIM];
    const int b = blockIdx.x, tid = threadIdx.x;
    if (tid < 256)
        ((float4*)ls)[tid] = ((const float4*)(g_last + (size_t)b * 2 * HDIM))[tid];
    __syncthreads();

    const int o = tid >> 2, q = tid & 3;
    const float4* wp = (const float4*)(Wfc + (size_t)o * (2 * HDIM)) + q * 64;
    const float4* lv = (const float4*)ls + q * 64;
    float acc = 0.f;
#pragma unroll 16
    for (int k = 0; k < 64; k++) {
        float4 w = __ldg(wp + k);
        float4 l = lv[k];
        acc += w.x * l.x + w.y * l.y + w.z * l.z + w.w * l.w;
    }
    acc += __shfl_xor_sync(0xffffffff, acc, 1);
    acc += __shfl_xor_sync(0xffffffff, acc, 2);
    if (q == 0) out[b * ODIM + o] = acc + bfc[o];
}

// ================================================================
extern "C" void kernel_launch(void* const* d_in, const int* in_sizes, int n_in,
                              void* d_out, int out_size)
{
    const float* x      = (const float*)d_in[0];
    const float* W_ih_f = (const float*)d_in[1];
    const float* W_hh_f = (const float*)d_in[2];
    const float* b_f    = (const float*)d_in[3];
    const float* W_ih_b = (const float*)d_in[4];
    const float* b_b    = (const float*)d_in[6];
    const float* W_fc   = (const float*)d_in[7];
    const float* b_fc   = (const float*)d_in[8];
    float* out = (float*)d_out;

    cudaFuncSetAttribute(gemm_xp_kernel,
                         cudaFuncAttributeMaxDynamicSharedMemorySize, GEMM_SMEM);
    cudaFuncSetAttribute(lstm_scan_kernel,
                         cudaFuncAttributeMaxDynamicSharedMemorySize, SCAN_SMEM);

    relu_kernel<<<2048, 256>>>(x);
    gemm_xp_kernel<<<dim3(G4 / BN, SEQ / 2), 256, GEMM_SMEM>>>(W_ih_f, b_f);
    bwd_last_kernel<<<dim3(BATCH, 2), 256>>>(W_ih_b, b_b);
    lstm_scan_kernel<<<SCAN_BLOCKS, 256, SCAN_SMEM>>>(W_hh_f);
    fc_kernel<<<BATCH, 512>>>(W_fc, b_fc, out);
}

// round 4
// speedup vs baseline: 1.0126x; 1.0126x over previous
#include <cuda_runtime.h>
#include <cstdint>

#define BATCH 64
#define SEQ   1024
#define IDIM  256
#define HDIM  512
#define ODIM  128
#define G4    2048

// ---------------- device scratch ----------------
__device__ float g_xr[(size_t)BATCH * SEQ * IDIM];     // relu(x)
__device__ float g_xp[(size_t)SEQ * BATCH * G4];       // forward input projection [t*64+b][4H]
__device__ float g_h[2][BATCH * HDIM];                 // double-buffered hidden state
__device__ float g_last[BATCH * 2 * HDIM];
__device__ unsigned long long g_bar;

typedef unsigned long long ull;

__device__ __forceinline__ void ffma2(ull &acc, ull a, ull b) {
    asm("fma.rn.f32x2 %0, %1, %2, %0;" : "+l"(acc) : "l"(a), "l"(b));
}
__device__ __forceinline__ float2 unpack2(ull v) {
    float2 f; asm("mov.b64 {%0, %1}, %2;" : "=f"(f.x), "=f"(f.y) : "l"(v)); return f;
}
__device__ __forceinline__ ull dup2(float a) {
    ull r; asm("mov.b64 %0, {%1, %1};" : "=l"(r) : "f"(a)); return r;
}
__device__ __forceinline__ float sigf(float v) { return 1.0f / (1.0f + expf(-v)); }

// ================================================================
// Kernel 0: xr = relu(x)
// ================================================================
__global__ void __launch_bounds__(256) relu_kernel(const float* __restrict__ x)
{
    const size_t n = (size_t)BATCH * SEQ * IDIM / 4;
    const float4* xin = (const float4*)x;
    float4* xo = (float4*)g_xr;
    for (size_t u = (size_t)blockIdx.x * blockDim.x + threadIdx.x; u < n;
         u += (size_t)gridDim.x * blockDim.x) {
        float4 v = __ldcs(xin + u);
        v.x = fmaxf(v.x, 0.f); v.y = fmaxf(v.y, 0.f);
        v.z = fmaxf(v.z, 0.f); v.w = fmaxf(v.w, 0.f);
        xo[u] = v;
    }
}

// ================================================================
// Kernel 1: xp = xr @ W_ih_f^T + b_f   (M=65536, N=2048, K=256)
// 128x64x32 tiles, double-buffered, 8x4 microtile with f32x2.
// ================================================================
#define BM 128
#define BN 64
#define BK 32
#define ALD 132
#define BLD 68
#define GEMM_SMEM ((2*BK*ALD + 2*BK*BLD) * 4)

__global__ void __launch_bounds__(256, 2) gemm_xp_kernel(
    const float* __restrict__ Wih, const float* __restrict__ bias)
{
    extern __shared__ float smg[];
    float* As = smg;                 // [2][BK][ALD]   [k][m]
    float* Bs = smg + 2 * BK * ALD;  // [2][BK][BLD]   [k][n]

    const int tid = threadIdx.x;
    const int n0  = blockIdx.x * BN;
    const int t0  = blockIdx.y * 2;
    const int tx  = tid & 15;        // n group (4 cols)
    const int ty  = tid >> 4;        // m group (8 rows)

    const int mA = tid >> 3, kqA = tid & 7;
    const float* aptr[4];
#pragma unroll
    for (int i = 0; i < 4; i++) {
        int m = mA + i * 32;
        aptr[i] = g_xr + ((size_t)(m & 63) * SEQ + t0 + (m >> 6)) * IDIM + kqA * 4;
    }
    const int nB = tid >> 3, kqB = tid & 7;
    const float* bptr[2];
#pragma unroll
    for (int i = 0; i < 2; i++)
        bptr[i] = Wih + (size_t)(n0 + nB + i * 32) * IDIM + kqB * 4;

    ull acc[8][2];
#pragma unroll
    for (int i = 0; i < 8; i++) { acc[i][0] = 0; acc[i][1] = 0; }

    float4 ra[4], rb[2];
#pragma unroll
    for (int i = 0; i < 4; i++) ra[i] = *(const float4*)(aptr[i]);
#pragma unroll
    for (int i = 0; i < 2; i++) rb[i] = *(const float4*)(bptr[i]);

#define STSAB(BUF) do{                                                     \
    float* ab = As + (BUF) * BK * ALD;                                     \
    _Pragma("unroll") for (int i = 0; i < 4; i++) {                        \
        int m = mA + i * 32;                                               \
        ab[(kqA*4+0)*ALD + m] = ra[i].x; ab[(kqA*4+1)*ALD + m] = ra[i].y;  \
        ab[(kqA*4+2)*ALD + m] = ra[i].z; ab[(kqA*4+3)*ALD + m] = ra[i].w; }\
    float* bb = Bs + (BUF) * BK * BLD;                                     \
    _Pragma("unroll") for (int i = 0; i < 2; i++) {                        \
        int n = nB + i * 32;                                               \
        bb[(kqB*4+0)*BLD + n] = rb[i].x; bb[(kqB*4+1)*BLD + n] = rb[i].y;  \
        bb[(kqB*4+2)*BLD + n] = rb[i].z; bb[(kqB*4+3)*BLD + n] = rb[i].w; }\
}while(0)

    STSAB(0);
    __syncthreads();

    int buf = 0;
#pragma unroll 1
    for (int it = 0; it < 8; it++) {
        if (it < 7) {
#pragma unroll
            for (int i = 0; i < 4; i++) ra[i] = *(const float4*)(aptr[i] + (it + 1) * BK);
#pragma unroll
            for (int i = 0; i < 2; i++) rb[i] = *(const float4*)(bptr[i] + (it + 1) * BK);
        }
        {
            const float* ab = As + buf * BK * ALD + ty * 8;
            const float* bb = Bs + buf * BK * BLD + tx * 4;
#pragma unroll
            for (int k = 0; k < BK; k++) {
                float4 a0 = *(const float4*)(ab + k * ALD);
                float4 a1 = *(const float4*)(ab + k * ALD + 4);
                ulonglong2 bq = *(const ulonglong2*)(bb + k * BLD);
                ull ad;
                ad = dup2(a0.x); ffma2(acc[0][0], ad, bq.x); ffma2(acc[0][1], ad, bq.y);
                ad = dup2(a0.y); ffma2(acc[1][0], ad, bq.x); ffma2(acc[1][1], ad, bq.y);
                ad = dup2(a0.z); ffma2(acc[2][0], ad, bq.x); ffma2(acc[2][1], ad, bq.y);
                ad = dup2(a0.w); ffma2(acc[3][0], ad, bq.x); ffma2(acc[3][1], ad, bq.y);
                ad = dup2(a1.x); ffma2(acc[4][0], ad, bq.x); ffma2(acc[4][1], ad, bq.y);
                ad = dup2(a1.y); ffma2(acc[5][0], ad, bq.x); ffma2(acc[5][1], ad, bq.y);
                ad = dup2(a1.z); ffma2(acc[6][0], ad, bq.x); ffma2(acc[6][1], ad, bq.y);
                ad = dup2(a1.w); ffma2(acc[7][0], ad, bq.x); ffma2(acc[7][1], ad, bq.y);
            }
        }
        if (it < 7) {
            STSAB(buf ^ 1);
            __syncthreads();
            buf ^= 1;
        }
    }

    const int ncol = n0 + tx * 4;
    float4 bv = *(const float4*)(bias + ncol);
#pragma unroll
    for (int i = 0; i < 8; i++) {
        int m = ty * 8 + i;
        int row = (t0 + (m >> 6)) * BATCH + (m & 63);
        float2 p0 = unpack2(acc[i][0]);
        float2 p1 = unpack2(acc[i][1]);
        float4 o;
        o.x = p0.x + bv.x; o.y = p0.y + bv.y;
        o.z = p1.x + bv.z; o.w = p1.y + bv.w;
        *(float4*)(g_xp + (size_t)row * G4 + ncol) = o;
    }
}

// ================================================================
// Kernel 2: backward-direction last hidden state (single step from 0).
// ================================================================
__global__ void __launch_bounds__(256) bwd_last_kernel(
    const float* __restrict__ Wb, const float* __restrict__ bb)
{
    __shared__ float xs[IDIM];
    const int b = blockIdx.x, tid = threadIdx.x;
    xs[tid] = g_xr[((size_t)b * SEQ + (SEQ - 1)) * IDIM + tid];
    __syncthreads();

    const int j = blockIdx.y * 256 + tid;
    const int cols[3] = { j, 2 * HDIM + j, 3 * HDIM + j };    // i, g, o
    float acc[3] = { bb[cols[0]], bb[cols[1]], bb[cols[2]] };
#pragma unroll
    for (int gi = 0; gi < 3; gi++) {
        const float4* wp = (const float4*)(Wb + (size_t)cols[gi] * IDIM);
        float s = 0.f;
#pragma unroll 8
        for (int k4 = 0; k4 < IDIM / 4; k4++) {
            float4 w = __ldg(wp + k4);
            float4 xv = *(const float4*)&xs[k4 * 4];
            s += w.x * xv.x + w.y * xv.y + w.z * xv.z + w.w * xv.w;
        }
        acc[gi] += s;
    }
    float cst = sigf(acc[0]) * tanhf(acc[1]);
    float h   = sigf(acc[2]) * tanhf(cst);
    g_last[b * (2 * HDIM) + HDIM + j] = h;
}

// ================================================================
// Kernel 3: persistent forward LSTM scan, h read DIRECTLY from L2.
// 128 blocks x 256 threads; block owns 16 gate cols (4 H-cols).
// Per thread: 2 batches x 2 cols. W slice in conflict-free SMEM.
// Per step: dot loop (LDS W + LDG.cg h + FFMA2), 1 syncthreads,
// cell update, h store, xp prefetch, grid barrier. No h staging.
// ================================================================
#define SCAN_BLOCKS 128

__device__ __forceinline__ void gridbar() {
    __syncthreads();
    if (threadIdx.x == 0) {
        __threadfence();
        ull old = atomicAdd(&g_bar, 1ull);
        ull target = (old / SCAN_BLOCKS + 1) * SCAN_BLOCKS;
        ull v;
        do {
            asm volatile("ld.acquire.gpu.global.u64 %0, [%1];"
                         : "=l"(v) : "l"(&g_bar) : "memory");
        } while (v < target);
    }
    __syncthreads();
}

__global__ void __launch_bounds__(256, 1) lstm_scan_kernel(const float* __restrict__ Whh)
{
    // W layout: per k-chunk kc (4 k values), 64 floats:
    //   [kc*64 + cp*4 + e]      = W[col(2cp)  ][kc*4+e]   (even local col)
    //   [kc*64 + 32 + cp*4 + e] = W[col(2cp+1)][kc*4+e]   (odd  local col)
    // -> both per-thread LDS.128 are conflict-free across cp lanes.
    __shared__ float ws[16 * HDIM];     // 32 KB
    __shared__ float gs[64 * 17];       // gate preacts

    const int tid = threadIdx.x;
    const int j0  = blockIdx.x * 4;

    // one-time W_hh slice load into interleaved layout
    for (int u = tid; u < 16 * (HDIM / 4); u += 256) {
        int cc = u & 15;                 // local col 0..15
        int k4 = u >> 4;                 // k-chunk 0..127
        int gate = cc >> 2, jl = cc & 3;
        float4 w = *(const float4*)(Whh + (size_t)(gate * HDIM + j0 + jl) * HDIM + k4 * 4);
        int p = cc >> 1;                 // cp
        float* dst = ws + k4 * 64 + (cc & 1) * 32 + p * 4;
        dst[0] = w.x; dst[1] = w.y; dst[2] = w.z; dst[3] = w.w;
    }

    // compute role: 2 batches x 2 cols
    const int cp = tid & 7, bp = tid >> 3;
    const int lc0 = cp * 2, lc1 = cp * 2 + 1;
    const int b0 = bp * 2,  b1 = bp * 2 + 1;
    const int col0 = (lc0 >> 2) * HDIM + j0 + (lc0 & 3);
    const int col1 = (lc1 >> 2) * HDIM + j0 + (lc1 & 3);
    const size_t tstride = (size_t)BATCH * G4;
    const float* xp00 = g_xp + (size_t)b0 * G4 + col0;
    const float* xp01 = g_xp + (size_t)b0 * G4 + col1;
    const float* xp10 = g_xp + (size_t)b1 * G4 + col0;
    const float* xp11 = g_xp + (size_t)b1 * G4 + col1;
    const float* wbase = ws + cp * 4;    // even col at +0, odd col at +32

    // update role
    const int ub = tid >> 2, ujl = tid & 3;
    float cstate = 0.f;
    float* hout0 = &g_h[0][ub * HDIM + j0 + ujl];
    float* hout1 = &g_h[1][ub * HDIM + j0 + ujl];

    float xv00 = __ldcs(xp00), xv01 = __ldcs(xp01);
    float xv10 = __ldcs(xp10), xv11 = __ldcs(xp11);
    __syncthreads();   // ws ready

    // ---- t = 0: h = 0 -> gates = xp ----
    gs[b0 * 17 + lc0] = xv00; gs[b0 * 17 + lc1] = xv01;
    gs[b1 * 17 + lc0] = xv10; gs[b1 * 17 + lc1] = xv11;
    __syncthreads();
    {
        float gi = gs[ub * 17 + 0 + ujl], gf = gs[ub * 17 + 4 + ujl];
        float gg = gs[ub * 17 + 8 + ujl], go = gs[ub * 17 + 12 + ujl];
        float i_ = sigf(gi), f_ = sigf(gf), gv = tanhf(gg), o_ = sigf(go);
        cstate = fmaf(f_, cstate, i_ * gv);
        float h = o_ * tanhf(cstate);
        __stcg(hout1, h);
    }
    xv00 = __ldcs(xp00 + tstride); xv01 = __ldcs(xp01 + tstride);
    xv10 = __ldcs(xp10 + tstride); xv11 = __ldcs(xp11 + tstride);
    gridbar();

#pragma unroll 1
    for (int t = 1; t < SEQ; t++) {
        const ulonglong2* hb0 = (const ulonglong2*)(g_h[t & 1] + b0 * HDIM);
        const ulonglong2* hb1 = (const ulonglong2*)(g_h[t & 1] + b1 * HDIM);
        float* hdst = (t & 1) ? hout0 : hout1;

        ull a000 = 0, a001 = 0, a010 = 0, a011 = 0;
        ull a100 = 0, a101 = 0, a110 = 0, a111 = 0;

#pragma unroll 4
        for (int kc = 0; kc < HDIM / 4; kc++) {
            ulonglong2 W0 = *(const ulonglong2*)(wbase + kc * 64);        // even col
            ulonglong2 W1 = *(const ulonglong2*)(wbase + kc * 64 + 32);   // odd col
            ulonglong2 H0 = __ldcg(hb0 + kc);
            ulonglong2 H1 = __ldcg(hb1 + kc);
            ffma2(a000, H0.x, W0.x); ffma2(a001, H0.y, W0.y);
            ffma2(a010, H0.x, W1.x); ffma2(a011, H0.y, W1.y);
            ffma2(a100, H1.x, W0.x); ffma2(a101, H1.y, W0.y);
            ffma2(a110, H1.x, W1.x); ffma2(a111, H1.y, W1.y);
        }

        {
            float2 p; float s00, s01, s10, s11;
            p = unpack2(a000); s00 = p.x + p.y; p = unpack2(a001); s00 += p.x + p.y;
            p = unpack2(a010); s01 = p.x + p.y; p = unpack2(a011); s01 += p.x + p.y;
            p = unpack2(a100); s10 = p.x + p.y; p = unpack2(a101); s10 += p.x + p.y;
            p = unpack2(a110); s11 = p.x + p.y; p = unpack2(a111); s11 += p.x + p.y;
            gs[b0 * 17 + lc0] = s00 + xv00; gs[b0 * 17 + lc1] = s01 + xv01;
            gs[b1 * 17 + lc0] = s10 + xv10; gs[b1 * 17 + lc1] = s11 + xv11;
        }
        __syncthreads();

        {
            float gi = gs[ub * 17 + 0 + ujl], gf = gs[ub * 17 + 4 + ujl];
            float gg = gs[ub * 17 + 8 + ujl], go = gs[ub * 17 + 12 + ujl];
            float i_ = sigf(gi), f_ = sigf(gf), gv = tanhf(gg), o_ = sigf(go);
            cstate = fmaf(f_, cstate, i_ * gv);
            float h = o_ * tanhf(cstate);
            __stcg(hdst, h);
            if (t == SEQ - 1)
                g_last[ub * (2 * HDIM) + j0 + ujl] = h;
        }

        if (t < SEQ - 1) {
            const size_t off = tstride * (size_t)(t + 1);
            xv00 = __ldcs(xp00 + off); xv01 = __ldcs(xp01 + off);
            xv10 = __ldcs(xp10 + off); xv11 = __ldcs(xp11 + off);
            gridbar();
        }
    }
}

// ================================================================
// Kernel 4: final FC. 64 blocks x 512 threads, 4 threads/output.
// ================================================================
__global__ void __launch_bounds__(512) fc_kernel(
    const float* __restrict__ Wfc, const float* __restrict__ bfc,
    float* __restrict__ out)
{
    __shared__ float ls[2 * HDIM];
    const int b = blockIdx.x, tid = threadIdx.x;
    if (tid < 256)
        ((float4*)ls)[tid] = ((const float4*)(g_last + (size_t)b * 2 * HDIM))[tid];
    __syncthreads();

    const int o = tid >> 2, q = tid & 3;
    const float4* wp = (const float4*)(Wfc + (size_t)o * (2 * HDIM)) + q * 64;
    const float4* lv = (const float4*)ls + q * 64;
    float acc = 0.f;
#pragma unroll 16
    for (int k = 0; k < 64; k++) {
        float4 w = __ldg(wp + k);
        float4 l = lv[k];
        acc += w.x * l.x + w.y * l.y + w.z * l.z + w.w * l.w;
    }
    acc += __shfl_xor_sync(0xffffffff, acc, 1);
    acc += __shfl_xor_sync(0xffffffff, acc, 2);
    if (q == 0) out[b * ODIM + o] = acc + bfc[o];
}

// ================================================================
extern "C" void kernel_launch(void* const* d_in, const int* in_sizes, int n_in,
                              void* d_out, int out_size)
{
    const float* x      = (const float*)d_in[0];
    const float* W_ih_f = (const float*)d_in[1];
    const float* W_hh_f = (const float*)d_in[2];
    const float* b_f    = (const float*)d_in[3];
    const float* W_ih_b = (const float*)d_in[4];
    const float* b_b    = (const float*)d_in[6];
    const float* W_fc   = (const float*)d_in[7];
    const float* b_fc   = (const float*)d_in[8];
    float* out = (float*)d_out;

    cudaFuncSetAttribute(gemm_xp_kernel,
                         cudaFuncAttributeMaxDynamicSharedMemorySize, GEMM_SMEM);

    relu_kernel<<<2048, 256>>>(x);
    gemm_xp_kernel<<<dim3(G4 / BN, SEQ / 2), 256, GEMM_SMEM>>>(W_ih_f, b_f);
    bwd_last_kernel<<<dim3(BATCH, 2), 256>>>(W_ih_b, b_b);
    lstm_scan_kernel<<<SCAN_BLOCKS, 256>>>(W_hh_f);
    fc_kernel<<<BATCH, 512>>>(W_fc, b_fc, out);
}

// round 5
// speedup vs baseline: 1.3281x; 1.3116x over previous
#include <cuda_runtime.h>
#include <cstdint>

#define BATCH 64
#define SEQ   1024
#define IDIM  256
#define HDIM  512
#define ODIM  128
#define G4    2048

// ---------------- device scratch ----------------
__device__ float g_xp[(size_t)SEQ * BATCH * G4];       // forward input projection [t*64+b][4H]
__device__ float g_h[2][BATCH * HDIM];                 // double-buffered hidden state
__device__ float g_last[BATCH * 2 * HDIM];
__device__ unsigned long long g_bar;

typedef unsigned long long ull;

__device__ __forceinline__ void ffma2(ull &acc, ull a, ull b) {
    asm("fma.rn.f32x2 %0, %1, %2, %0;" : "+l"(acc) : "l"(a), "l"(b));
}
__device__ __forceinline__ float2 unpack2(ull v) {
    float2 f; asm("mov.b64 {%0, %1}, %2;" : "=f"(f.x), "=f"(f.y) : "l"(v)); return f;
}
__device__ __forceinline__ ull dup2(float a) {
    ull r; asm("mov.b64 %0, {%1, %1};" : "=l"(r) : "f"(a)); return r;
}
__device__ __forceinline__ float sigf(float v) { return 1.0f / (1.0f + expf(-v)); }

// ================================================================
// Kernel 1: xp = relu(x) @ W_ih_f^T + b_f   (M=65536, N=2048, K=256)
// 128x64x32 tiles, double-buffered, 8x4 microtile with f32x2.
// relu fused into the A-tile store.
// ================================================================
#define BM 128
#define BN 64
#define BK 32
#define ALD 132
#define BLD 68
#define GEMM_SMEM ((2*BK*ALD + 2*BK*BLD) * 4)

__global__ void __launch_bounds__(256, 2) gemm_xp_kernel(
    const float* __restrict__ x,
    const float* __restrict__ Wih, const float* __restrict__ bias)
{
    extern __shared__ float smg[];
    float* As = smg;                 // [2][BK][ALD]   [k][m]
    float* Bs = smg + 2 * BK * ALD;  // [2][BK][BLD]   [k][n]

    const int tid = threadIdx.x;
    const int n0  = blockIdx.x * BN;
    const int t0  = blockIdx.y * 2;
    const int tx  = tid & 15;        // n group (4 cols)
    const int ty  = tid >> 4;        // m group (8 rows)

    const int mA = tid >> 3, kqA = tid & 7;
    const float* aptr[4];
#pragma unroll
    for (int i = 0; i < 4; i++) {
        int m = mA + i * 32;
        aptr[i] = x + ((size_t)(m & 63) * SEQ + t0 + (m >> 6)) * IDIM + kqA * 4;
    }
    const int nB = tid >> 3, kqB = tid & 7;
    const float* bptr[2];
#pragma unroll
    for (int i = 0; i < 2; i++)
        bptr[i] = Wih + (size_t)(n0 + nB + i * 32) * IDIM + kqB * 4;

    ull acc[8][2];
#pragma unroll
    for (int i = 0; i < 8; i++) { acc[i][0] = 0; acc[i][1] = 0; }

    float4 ra[4], rb[2];
#pragma unroll
    for (int i = 0; i < 4; i++) ra[i] = *(const float4*)(aptr[i]);
#pragma unroll
    for (int i = 0; i < 2; i++) rb[i] = *(const float4*)(bptr[i]);

#define STSAB(BUF) do{                                                     \
    float* ab = As + (BUF) * BK * ALD;                                     \
    _Pragma("unroll") for (int i = 0; i < 4; i++) {                        \
        int m = mA + i * 32;                                               \
        ab[(kqA*4+0)*ALD + m] = fmaxf(ra[i].x, 0.f);                       \
        ab[(kqA*4+1)*ALD + m] = fmaxf(ra[i].y, 0.f);                       \
        ab[(kqA*4+2)*ALD + m] = fmaxf(ra[i].z, 0.f);                       \
        ab[(kqA*4+3)*ALD + m] = fmaxf(ra[i].w, 0.f); }                     \
    float* bb = Bs + (BUF) * BK * BLD;                                     \
    _Pragma("unroll") for (int i = 0; i < 2; i++) {                        \
        int n = nB + i * 32;                                               \
        bb[(kqB*4+0)*BLD + n] = rb[i].x; bb[(kqB*4+1)*BLD + n] = rb[i].y;  \
        bb[(kqB*4+2)*BLD + n] = rb[i].z; bb[(kqB*4+3)*BLD + n] = rb[i].w; }\
}while(0)

    STSAB(0);
    __syncthreads();

    int buf = 0;
#pragma unroll 1
    for (int it = 0; it < 8; it++) {
        if (it < 7) {
#pragma unroll
            for (int i = 0; i < 4; i++) ra[i] = *(const float4*)(aptr[i] + (it + 1) * BK);
#pragma unroll
            for (int i = 0; i < 2; i++) rb[i] = *(const float4*)(bptr[i] + (it + 1) * BK);
        }
        {
            const float* ab = As + buf * BK * ALD + ty * 8;
            const float* bb = Bs + buf * BK * BLD + tx * 4;
#pragma unroll
            for (int k = 0; k < BK; k++) {
                float4 a0 = *(const float4*)(ab + k * ALD);
                float4 a1 = *(const float4*)(ab + k * ALD + 4);
                ulonglong2 bq = *(const ulonglong2*)(bb + k * BLD);
                ull ad;
                ad = dup2(a0.x); ffma2(acc[0][0], ad, bq.x); ffma2(acc[0][1], ad, bq.y);
                ad = dup2(a0.y); ffma2(acc[1][0], ad, bq.x); ffma2(acc[1][1], ad, bq.y);
                ad = dup2(a0.z); ffma2(acc[2][0], ad, bq.x); ffma2(acc[2][1], ad, bq.y);
                ad = dup2(a0.w); ffma2(acc[3][0], ad, bq.x); ffma2(acc[3][1], ad, bq.y);
                ad = dup2(a1.x); ffma2(acc[4][0], ad, bq.x); ffma2(acc[4][1], ad, bq.y);
                ad = dup2(a1.y); ffma2(acc[5][0], ad, bq.x); ffma2(acc[5][1], ad, bq.y);
                ad = dup2(a1.z); ffma2(acc[6][0], ad, bq.x); ffma2(acc[6][1], ad, bq.y);
                ad = dup2(a1.w); ffma2(acc[7][0], ad, bq.x); ffma2(acc[7][1], ad, bq.y);
            }
        }
        if (it < 7) {
            STSAB(buf ^ 1);
            __syncthreads();
            buf ^= 1;
        }
    }

    const int ncol = n0 + tx * 4;
    float4 bv = *(const float4*)(bias + ncol);
#pragma unroll
    for (int i = 0; i < 8; i++) {
        int m = ty * 8 + i;
        int row = (t0 + (m >> 6)) * BATCH + (m & 63);
        float2 p0 = unpack2(acc[i][0]);
        float2 p1 = unpack2(acc[i][1]);
        float4 o;
        o.x = p0.x + bv.x; o.y = p0.y + bv.y;
        o.z = p1.x + bv.z; o.w = p1.y + bv.w;
        *(float4*)(g_xp + (size_t)row * G4 + ncol) = o;
    }
}

// ================================================================
// Kernel 2: backward-direction last hidden state (single step from 0).
// ================================================================
__global__ void __launch_bounds__(256) bwd_last_kernel(
    const float* __restrict__ x,
    const float* __restrict__ Wb, const float* __restrict__ bb)
{
    __shared__ float xs[IDIM];
    const int b = blockIdx.x, tid = threadIdx.x;
    xs[tid] = fmaxf(x[((size_t)b * SEQ + (SEQ - 1)) * IDIM + tid], 0.f);
    __syncthreads();

    const int j = blockIdx.y * 256 + tid;
    const int cols[3] = { j, 2 * HDIM + j, 3 * HDIM + j };    // i, g, o
    float acc[3] = { bb[cols[0]], bb[cols[1]], bb[cols[2]] };
#pragma unroll
    for (int gi = 0; gi < 3; gi++) {
        const float4* wp = (const float4*)(Wb + (size_t)cols[gi] * IDIM);
        float s = 0.f;
#pragma unroll 8
        for (int k4 = 0; k4 < IDIM / 4; k4++) {
            float4 w = __ldg(wp + k4);
            float4 xv = *(const float4*)&xs[k4 * 4];
            s += w.x * xv.x + w.y * xv.y + w.z * xv.z + w.w * xv.w;
        }
        acc[gi] += s;
    }
    float cst = sigf(acc[0]) * tanhf(acc[1]);
    float h   = sigf(acc[2]) * tanhf(cst);
    g_last[b * (2 * HDIM) + HDIM + j] = h;
}

// ================================================================
// Kernel 3: persistent forward LSTM scan with SMEM-staged h.
// 128 blocks x 256 threads; block owns 16 gate cols (4 H-cols).
// Per step: stage full h (128 KB) into SMEM (coalesced LDG.cg),
// one sync, conflict-free LDS dot loop (2 batches x 2 cols / thread),
// gate sync, cell update, xp prefetch, ONE grid barrier.
// ================================================================
#define SCAN_BLOCKS 128
#define HS 516                            // 512 + 4 pad -> conflict-free LDS.128
#define SCAN_SMEM ((16*HDIM + 64*HS + 64*17) * 4)

__device__ __forceinline__ void gridbar() {
    __syncthreads();
    if (threadIdx.x == 0) {
        __threadfence();
        ull old = atomicAdd(&g_bar, 1ull);
        ull target = (old / SCAN_BLOCKS + 1) * SCAN_BLOCKS;
        ull v;
        do {
            asm volatile("ld.acquire.gpu.global.u64 %0, [%1];"
                         : "=l"(v) : "l"(&g_bar) : "memory");
        } while (v < target);
    }
    __syncthreads();
}

__global__ void __launch_bounds__(256, 1) lstm_scan_kernel(const float* __restrict__ Whh)
{
    extern __shared__ float sm[];
    float* ws  = sm;                      // [16 cols][512 k] interleaved, conflict-free
    float* hsm = sm + 16 * HDIM;          // [64][HS] staged h
    float* gs  = hsm + 64 * HS;           // [64][17] gate preacts

    const int tid = threadIdx.x;
    const int j0  = blockIdx.x * 4;

    // one-time W_hh slice load into interleaved layout:
    //   ws[kc*64 + (cc&1)*32 + (cc>>1)*4 + e] = W[col cc][kc*4+e]
    for (int u = tid; u < 16 * (HDIM / 4); u += 256) {
        int cc = u & 15;                 // local col 0..15
        int k4 = u >> 4;                 // k-chunk 0..127
        int gate = cc >> 2, jl = cc & 3;
        float4 w = *(const float4*)(Whh + (size_t)(gate * HDIM + j0 + jl) * HDIM + k4 * 4);
        float* dst = ws + k4 * 64 + (cc & 1) * 32 + (cc >> 1) * 4;
        dst[0] = w.x; dst[1] = w.y; dst[2] = w.z; dst[3] = w.w;
    }

    // compute role: 2 batches x 2 cols
    const int cp = tid & 7, bp = tid >> 3;
    const int lc0 = cp * 2, lc1 = cp * 2 + 1;
    const int b0 = bp * 2,  b1 = bp * 2 + 1;
    const int col0 = (lc0 >> 2) * HDIM + j0 + (lc0 & 3);
    const int col1 = (lc1 >> 2) * HDIM + j0 + (lc1 & 3);
    const size_t tstride = (size_t)BATCH * G4;
    const float* xp00 = g_xp + (size_t)b0 * G4 + col0;
    const float* xp01 = g_xp + (size_t)b0 * G4 + col1;
    const float* xp10 = g_xp + (size_t)b1 * G4 + col0;
    const float* xp11 = g_xp + (size_t)b1 * G4 + col1;
    const float* wbase = ws + cp * 4;    // even col at +0, odd col at +32
    const float* hb0 = hsm + b0 * HS;
    const float* hb1 = hsm + b1 * HS;

    // update role
    const int ub = tid >> 2, ujl = tid & 3;
    float cstate = 0.f;
    float* hout0 = &g_h[0][ub * HDIM + j0 + ujl];
    float* hout1 = &g_h[1][ub * HDIM + j0 + ujl];

    float xv00 = __ldcs(xp00), xv01 = __ldcs(xp01);
    float xv10 = __ldcs(xp10), xv11 = __ldcs(xp11);
    __syncthreads();   // ws ready

    // ---- t = 0: h = 0 -> gates = xp ----
    gs[b0 * 17 + lc0] = xv00; gs[b0 * 17 + lc1] = xv01;
    gs[b1 * 17 + lc0] = xv10; gs[b1 * 17 + lc1] = xv11;
    __syncthreads();
    {
        float gi = gs[ub * 17 + 0 + ujl], gf = gs[ub * 17 + 4 + ujl];
        float gg = gs[ub * 17 + 8 + ujl], go = gs[ub * 17 + 12 + ujl];
        float i_ = sigf(gi), f_ = sigf(gf), gv = tanhf(gg), o_ = sigf(go);
        cstate = fmaf(f_, cstate, i_ * gv);
        float h = o_ * tanhf(cstate);
        __stcg(hout1, h);
    }
    xv00 = __ldcs(xp00 + tstride); xv01 = __ldcs(xp01 + tstride);
    xv10 = __ldcs(xp10 + tstride); xv11 = __ldcs(xp11 + tstride);
    gridbar();

#pragma unroll 1
    for (int t = 1; t < SEQ; t++) {
        const float4* src = (const float4*)g_h[t & 1];
        float* hdst = (t & 1) ? hout0 : hout1;

        // ---- stage h into SMEM: 32 float4 per thread, coalesced ----
#pragma unroll 8
        for (int i = 0; i < 32; i++) {
            int u = tid + i * 256;
            float4 v = __ldcg(src + u);
            int b  = u >> 7;              // 128 float4 per batch row
            int kq = (u & 127) << 2;
            *(float4*)(hsm + b * HS + kq) = v;
        }
        __syncthreads();

        // ---- dot products, all from SMEM, conflict-free ----
        ull a000 = 0, a001 = 0, a010 = 0, a011 = 0;
        ull a100 = 0, a101 = 0, a110 = 0, a111 = 0;
#pragma unroll 8
        for (int kc = 0; kc < HDIM / 4; kc++) {
            ulonglong2 W0 = *(const ulonglong2*)(wbase + kc * 64);        // even col
            ulonglong2 W1 = *(const ulonglong2*)(wbase + kc * 64 + 32);   // odd col
            ulonglong2 H0 = *(const ulonglong2*)(hb0 + kc * 4);
            ulonglong2 H1 = *(const ulonglong2*)(hb1 + kc * 4);
            ffma2(a000, H0.x, W0.x); ffma2(a001, H0.y, W0.y);
            ffma2(a010, H0.x, W1.x); ffma2(a011, H0.y, W1.y);
            ffma2(a100, H1.x, W0.x); ffma2(a101, H1.y, W0.y);
            ffma2(a110, H1.x, W1.x); ffma2(a111, H1.y, W1.y);
        }

        {
            float2 p; float s00, s01, s10, s11;
            p = unpack2(a000); s00 = p.x + p.y; p = unpack2(a001); s00 += p.x + p.y;
            p = unpack2(a010); s01 = p.x + p.y; p = unpack2(a011); s01 += p.x + p.y;
            p = unpack2(a100); s10 = p.x + p.y; p = unpack2(a101); s10 += p.x + p.y;
            p = unpack2(a110); s11 = p.x + p.y; p = unpack2(a111); s11 += p.x + p.y;
            gs[b0 * 17 + lc0] = s00 + xv00; gs[b0 * 17 + lc1] = s01 + xv01;
            gs[b1 * 17 + lc0] = s10 + xv10; gs[b1 * 17 + lc1] = s11 + xv11;
        }
        __syncthreads();

        // ---- cell update ----
        {
            float gi = gs[ub * 17 + 0 + ujl], gf = gs[ub * 17 + 4 + ujl];
            float gg = gs[ub * 17 + 8 + ujl], go = gs[ub * 17 + 12 + ujl];
            float i_ = sigf(gi), f_ = sigf(gf), gv = tanhf(gg), o_ = sigf(go);
            cstate = fmaf(f_, cstate, i_ * gv);
            float h = o_ * tanhf(cstate);
            __stcg(hdst, h);
            if (t == SEQ - 1)
                g_last[ub * (2 * HDIM) + j0 + ujl] = h;
        }

        if (t < SEQ - 1) {
            const size_t off = tstride * (size_t)(t + 1);
            xv00 = __ldcs(xp00 + off); xv01 = __ldcs(xp01 + off);
            xv10 = __ldcs(xp10 + off); xv11 = __ldcs(xp11 + off);
            gridbar();
        }
    }
}

// ================================================================
// Kernel 4: final FC. 64 blocks x 512 threads, 4 threads/output.
// ================================================================
__global__ void __launch_bounds__(512) fc_kernel(
    const float* __restrict__ Wfc, const float* __restrict__ bfc,
    float* __restrict__ out)
{
    __shared__ float ls[2 * HDIM];
    const int b = blockIdx.x, tid = threadIdx.x;
    if (tid < 256)
        ((float4*)ls)[tid] = ((const float4*)(g_last + (size_t)b * 2 * HDIM))[tid];
    __syncthreads();

    const int o = tid >> 2, q = tid & 3;
    const float4* wp = (const float4*)(Wfc + (size_t)o * (2 * HDIM)) + q * 64;
    const float4* lv = (const float4*)ls + q * 64;
    float acc = 0.f;
#pragma unroll 16
    for (int k = 0; k < 64; k++) {
        float4 w = __ldg(wp + k);
        float4 l = lv[k];
        acc += w.x * l.x + w.y * l.y + w.z * l.z + w.w * l.w;
    }
    acc += __shfl_xor_sync(0xffffffff, acc, 1);
    acc += __shfl_xor_sync(0xffffffff, acc, 2);
    if (q == 0) out[b * ODIM + o] = acc + bfc[o];
}

// ================================================================
extern "C" void kernel_launch(void* const* d_in, const int* in_sizes, int n_in,
                              void* d_out, int out_size)
{
    const float* x      = (const float*)d_in[0];
    const float* W_ih_f = (const float*)d_in[1];
    const float* W_hh_f = (const float*)d_in[2];
    const float* b_f    = (const float*)d_in[3];
    const float* W_ih_b = (const float*)d_in[4];
    const float* b_b    = (const float*)d_in[6];
    const float* W_fc   = (const float*)d_in[7];
    const float* b_fc   = (const float*)d_in[8];
    float* out = (float*)d_out;

    cudaFuncSetAttribute(gemm_xp_kernel,
                         cudaFuncAttributeMaxDynamicSharedMemorySize, GEMM_SMEM);
    cudaFuncSetAttribute(lstm_scan_kernel,
                         cudaFuncAttributeMaxDynamicSharedMemorySize, SCAN_SMEM);

    gemm_xp_kernel<<<dim3(G4 / BN, SEQ / 2), 256, GEMM_SMEM>>>(x, W_ih_f, b_f);
    bwd_last_kernel<<<dim3(BATCH, 2), 256>>>(x, W_ih_b, b_b);
    lstm_scan_kernel<<<SCAN_BLOCKS, 256, SCAN_SMEM>>>(W_hh_f);
    fc_kernel<<<BATCH, 512>>>(W_fc, b_fc, out);
}

// round 7
// speedup vs baseline: 1.4677x; 1.1051x over previous
#include <cuda_runtime.h>
#include <cstdint>

#define BATCH 64
#define SEQ   1024
#define IDIM  256
#define HDIM  512
#define ODIM  128
#define G4    2048

// ---------------- device scratch ----------------
__device__ float g_xp[(size_t)SEQ * BATCH * G4];       // forward input projection [t*64+b][4H]
__device__ float g_h[2][BATCH * HDIM];                 // double-buffered hidden state
__device__ float g_last[BATCH * 2 * HDIM];
__device__ unsigned long long g_flags[128][16];        // padded per-block barrier flags (128B rows)

typedef unsigned long long ull;

__device__ __forceinline__ void ffma2(ull &acc, ull a, ull b) {
    asm("fma.rn.f32x2 %0, %1, %2, %0;" : "+l"(acc) : "l"(a), "l"(b));
}
__device__ __forceinline__ float2 unpack2(ull v) {
    float2 f; asm("mov.b64 {%0, %1}, %2;" : "=f"(f.x), "=f"(f.y) : "l"(v)); return f;
}
__device__ __forceinline__ ull dup2(float a) {
    ull r; asm("mov.b64 %0, {%1, %1};" : "=l"(r) : "f"(a)); return r;
}
__device__ __forceinline__ float sigf(float v) { return 1.0f / (1.0f + expf(-v)); }

// ================================================================
// Kernel 1: xp = relu(x) @ W_ih_f^T + b_f   (M=65536, N=2048, K=256)
// 128x64x32 tiles, double-buffered, 8x4 microtile with f32x2.
// ================================================================
#define BM 128
#define BN 64
#define BK 32
#define ALD 132
#define BLD 68
#define GEMM_SMEM ((2*BK*ALD + 2*BK*BLD) * 4)

__global__ void __launch_bounds__(256, 2) gemm_xp_kernel(
    const float* __restrict__ x,
    const float* __restrict__ Wih, const float* __restrict__ bias)
{
    extern __shared__ float smg[];
    float* As = smg;                 // [2][BK][ALD]   [k][m]
    float* Bs = smg + 2 * BK * ALD;  // [2][BK][BLD]   [k][n]

    const int tid = threadIdx.x;
    const int n0  = blockIdx.x * BN;
    const int t0  = blockIdx.y * 2;
    const int tx  = tid & 15;        // n group (4 cols)
    const int ty  = tid >> 4;        // m group (8 rows)

    const int mA = tid >> 3, kqA = tid & 7;
    const float* aptr[4];
#pragma unroll
    for (int i = 0; i < 4; i++) {
        int m = mA + i * 32;
        aptr[i] = x + ((size_t)(m & 63) * SEQ + t0 + (m >> 6)) * IDIM + kqA * 4;
    }
    const int nB = tid >> 3, kqB = tid & 7;
    const float* bptr[2];
#pragma unroll
    for (int i = 0; i < 2; i++)
        bptr[i] = Wih + (size_t)(n0 + nB + i * 32) * IDIM + kqB * 4;

    ull acc[8][2];
#pragma unroll
    for (int i = 0; i < 8; i++) { acc[i][0] = 0; acc[i][1] = 0; }

    float4 ra[4], rb[2];
#pragma unroll
    for (int i = 0; i < 4; i++) ra[i] = *(const float4*)(aptr[i]);
#pragma unroll
    for (int i = 0; i < 2; i++) rb[i] = *(const float4*)(bptr[i]);

#define STSAB(BUF) do{                                                     \
    float* ab = As + (BUF) * BK * ALD;                                     \
    _Pragma("unroll") for (int i = 0; i < 4; i++) {                        \
        int m = mA + i * 32;                                               \
        ab[(kqA*4+0)*ALD + m] = fmaxf(ra[i].x, 0.f);                       \
        ab[(kqA*4+1)*ALD + m] = fmaxf(ra[i].y, 0.f);                       \
        ab[(kqA*4+2)*ALD + m] = fmaxf(ra[i].z, 0.f);                       \
        ab[(kqA*4+3)*ALD + m] = fmaxf(ra[i].w, 0.f); }                     \
    float* bb = Bs + (BUF) * BK * BLD;                                     \
    _Pragma("unroll") for (int i = 0; i < 2; i++) {                        \
        int n = nB + i * 32;                                               \
        bb[(kqB*4+0)*BLD + n] = rb[i].x; bb[(kqB*4+1)*BLD + n] = rb[i].y;  \
        bb[(kqB*4+2)*BLD + n] = rb[i].z; bb[(kqB*4+3)*BLD + n] = rb[i].w; }\
}while(0)

    STSAB(0);
    __syncthreads();

    int buf = 0;
#pragma unroll 1
    for (int it = 0; it < 8; it++) {
        if (it < 7) {
#pragma unroll
            for (int i = 0; i < 4; i++) ra[i] = *(const float4*)(aptr[i] + (it + 1) * BK);
#pragma unroll
            for (int i = 0; i < 2; i++) rb[i] = *(const float4*)(bptr[i] + (it + 1) * BK);
        }
        {
            const float* ab = As + buf * BK * ALD + ty * 8;
            const float* bb = Bs + buf * BK * BLD + tx * 4;
#pragma unroll
            for (int k = 0; k < BK; k++) {
                float4 a0 = *(const float4*)(ab + k * ALD);
                float4 a1 = *(const float4*)(ab + k * ALD + 4);
                ulonglong2 bq = *(const ulonglong2*)(bb + k * BLD);
                ull ad;
                ad = dup2(a0.x); ffma2(acc[0][0], ad, bq.x); ffma2(acc[0][1], ad, bq.y);
                ad = dup2(a0.y); ffma2(acc[1][0], ad, bq.x); ffma2(acc[1][1], ad, bq.y);
                ad = dup2(a0.z); ffma2(acc[2][0], ad, bq.x); ffma2(acc[2][1], ad, bq.y);
                ad = dup2(a0.w); ffma2(acc[3][0], ad, bq.x); ffma2(acc[3][1], ad, bq.y);
                ad = dup2(a1.x); ffma2(acc[4][0], ad, bq.x); ffma2(acc[4][1], ad, bq.y);
                ad = dup2(a1.y); ffma2(acc[5][0], ad, bq.x); ffma2(acc[5][1], ad, bq.y);
                ad = dup2(a1.z); ffma2(acc[6][0], ad, bq.x); ffma2(acc[6][1], ad, bq.y);
                ad = dup2(a1.w); ffma2(acc[7][0], ad, bq.x); ffma2(acc[7][1], ad, bq.y);
            }
        }
        if (it < 7) {
            STSAB(buf ^ 1);
            __syncthreads();
            buf ^= 1;
        }
    }

    const int ncol = n0 + tx * 4;
    float4 bv = *(const float4*)(bias + ncol);
#pragma unroll
    for (int i = 0; i < 8; i++) {
        int m = ty * 8 + i;
        int row = (t0 + (m >> 6)) * BATCH + (m & 63);
        float2 p0 = unpack2(acc[i][0]);
        float2 p1 = unpack2(acc[i][1]);
        float4 o;
        o.x = p0.x + bv.x; o.y = p0.y + bv.y;
        o.z = p1.x + bv.z; o.w = p1.y + bv.w;
        *(float4*)(g_xp + (size_t)row * G4 + ncol) = o;
    }
}

// ================================================================
// Kernel 2: backward-direction last hidden state (single step from 0).
// ================================================================
__global__ void __launch_bounds__(256) bwd_last_kernel(
    const float* __restrict__ x,
    const float* __restrict__ Wb, const float* __restrict__ bb)
{
    __shared__ float xs[IDIM];
    const int b = blockIdx.x, tid = threadIdx.x;
    xs[tid] = fmaxf(x[((size_t)b * SEQ + (SEQ - 1)) * IDIM + tid], 0.f);
    __syncthreads();

    const int j = blockIdx.y * 256 + tid;
    const int cols[3] = { j, 2 * HDIM + j, 3 * HDIM + j };    // i, g, o
    float acc[3] = { bb[cols[0]], bb[cols[1]], bb[cols[2]] };
#pragma unroll
    for (int gi = 0; gi < 3; gi++) {
        const float4* wp = (const float4*)(Wb + (size_t)cols[gi] * IDIM);
        float s = 0.f;
#pragma unroll 8
        for (int k4 = 0; k4 < IDIM / 4; k4++) {
            float4 w = __ldg(wp + k4);
            float4 xv = *(const float4*)&xs[k4 * 4];
            s += w.x * xv.x + w.y * xv.y + w.z * xv.z + w.w * xv.w;
        }
        acc[gi] += s;
    }
    float cst = sigf(acc[0]) * tanhf(acc[1]);
    float h   = sigf(acc[2]) * tanhf(cst);
    g_last[b * (2 * HDIM) + HDIM + j] = h;
}

// ================================================================
// Kernel 3: persistent forward LSTM scan, 2-D partition.
// 128 blocks = 32 j-groups x 4 batch-groups. Block owns
// 16 H-cols (64 gate cols) x 16 batches. W slice 128 KB in SMEM;
// staged h only 32 KB/step. All h SMEM traffic is 8-byte ops
// (HSP=514: conflict-free spread, 8B-aligned for every row).
// Barrier: per-block padded flags with ABSOLUTE targets (t+1) from
// zeroed flags; a cleanup kernel re-zeroes flags after the scan so
// every launch/graph replay starts identically. No atomics.
// ================================================================
#define SCAN_BLOCKS 128
#define HSP 514                           // pitch: 2*HSP mod 32 == 4 -> conflict-free; 8B-aligned
#define GSP 68
#define SCAN_SMEM ((64*HDIM + 16*HSP + 16*GSP) * 4)

__global__ void __launch_bounds__(256, 1) lstm_scan_kernel(const float* __restrict__ Whh)
{
    extern __shared__ float sm[];
    float* ws = sm;                       // [128 kc][256] W slice, interleaved
    float* hs = sm + 64 * HDIM;           // [16][HSP] staged h
    float* gs = hs + 16 * HSP;            // [16][GSP] gate preacts

    const int tid = threadIdx.x;
    const int bid = blockIdx.x;
    const int jg  = bid >> 2;             // 0..31  -> H-cols [jg*16, jg*16+16)
    const int bg  = bid & 3;              // 0..3   -> batches [bg*16, bg*16+16)

    // ---- one-time W_hh slice load, interleaved conflict-free layout ----
    // ws[kc*256 + (lc&1)*128 + (lc>>1)*4 + e] = Whh[grow(lc)][kc*4+e]
    for (int u = tid; u < 64 * (HDIM / 4); u += 256) {
        int lc = u & 63;                  // local gate col 0..63
        int kc = u >> 6;                  // k-chunk 0..127
        int gate = lc >> 4, jl = lc & 15;
        int grow = gate * HDIM + jg * 16 + jl;
        float4 w = *(const float4*)(Whh + (size_t)grow * HDIM + kc * 4);
        float* dst = ws + kc * 256 + (lc & 1) * 128 + (lc >> 1) * 4;
        dst[0] = w.x; dst[1] = w.y; dst[2] = w.z; dst[3] = w.w;
    }

    // dot role: cp = col pair (cols 2cp, 2cp+1), bp = batch pair (2bp, 2bp+1)
    const int cp = tid >> 3, bp = tid & 7;
    const int lc0 = 2 * cp, lc1 = 2 * cp + 1;
    const int lb0 = 2 * bp, lb1 = 2 * bp + 1;
    const int gcol0 = (lc0 >> 4) * HDIM + jg * 16 + (lc0 & 15);
    const int gcol1 = (lc1 >> 4) * HDIM + jg * 16 + (lc1 & 15);
    const size_t tstride = (size_t)BATCH * G4;
    const float* xp00 = g_xp + (size_t)(bg * 16 + lb0) * G4 + gcol0;
    const float* xp01 = g_xp + (size_t)(bg * 16 + lb0) * G4 + gcol1;
    const float* xp10 = g_xp + (size_t)(bg * 16 + lb1) * G4 + gcol0;
    const float* xp11 = g_xp + (size_t)(bg * 16 + lb1) * G4 + gcol1;
    const float* wev = ws + cp * 4;        // even col; +128 floats for odd col
    const ull* hq0 = (const ull*)(hs + lb0 * HSP);   // 8B-aligned
    const ull* hq1 = (const ull*)(hs + lb1 * HSP);   // 8B-aligned

    // update role: thread owns (batch ub, j-col uj)
    const int ub = tid >> 4, uj = tid & 15;
    float cstate = 0.f;
    const int hidx = (bg * 16 + ub) * HDIM + jg * 16 + uj;
    float* hout0 = &g_h[0][hidx];
    float* hout1 = &g_h[1][hidx];

    float xv00 = __ldcs(xp00), xv01 = __ldcs(xp01);
    float xv10 = __ldcs(xp10), xv11 = __ldcs(xp11);
    __syncthreads();   // ws ready

    // ---- t = 0: h = 0 -> gates = xp ----
    gs[lb0 * GSP + lc0] = xv00; gs[lb0 * GSP + lc1] = xv01;
    gs[lb1 * GSP + lc0] = xv10; gs[lb1 * GSP + lc1] = xv11;
    __syncthreads();
    {
        float gi = gs[ub * GSP + 0 + uj],  gf = gs[ub * GSP + 16 + uj];
        float gg = gs[ub * GSP + 32 + uj], go = gs[ub * GSP + 48 + uj];
        float i_ = sigf(gi), f_ = sigf(gf), gv = tanhf(gg), o_ = sigf(go);
        cstate = fmaf(f_, cstate, i_ * gv);
        float h = o_ * tanhf(cstate);
        __stcg(hout1, h);
    }
    xv00 = __ldcs(xp00 + tstride); xv01 = __ldcs(xp01 + tstride);
    xv10 = __ldcs(xp10 + tstride); xv11 = __ldcs(xp11 + tstride);

#define FLAGBAR(VAL) do{                                                       \
    __syncthreads();                                                           \
    if (tid == 0)                                                              \
        asm volatile("st.release.gpu.global.u64 [%0], %1;"                     \
                     :: "l"(&g_flags[bid][0]), "l"((ull)(VAL)) : "memory");    \
    if (tid < 128) {                                                           \
        ull v;                                                                 \
        do {                                                                   \
            asm volatile("ld.acquire.gpu.global.u64 %0, [%1];"                 \
                         : "=l"(v) : "l"(&g_flags[tid][0]) : "memory");        \
        } while (v < (ull)(VAL));                                              \
    }                                                                          \
    __syncthreads();                                                           \
}while(0)

    FLAGBAR(1);

#pragma unroll 1
    for (int t = 1; t < SEQ; t++) {
        const ulonglong2* src = (const ulonglong2*)(g_h[t & 1] + (size_t)bg * 16 * HDIM);
        float* hdst = (t & 1) ? hout0 : hout1;

        // ---- stage this block's 16 h rows (32 KB): 8x16B per thread, 8B STS ----
#pragma unroll
        for (int i = 0; i < 8; i++) {
            int u = tid + i * 256;                 // u indexes 16B chunks
            ulonglong2 v = __ldcg(src + u);
            int b  = u >> 7;                       // 128 x 16B per batch row
            int kq = (u & 127) << 2;               // float offset (multiple of 4)
            ull* d = (ull*)(hs + b * HSP + kq);    // 8B-aligned
            d[0] = v.x; d[1] = v.y;
        }
        __syncthreads();

        // ---- dot products from SMEM (W: LDS.128, h: LDS.64, conflict-free) ----
        ull a000 = 0, a001 = 0, a010 = 0, a011 = 0;
        ull a100 = 0, a101 = 0, a110 = 0, a111 = 0;
#pragma unroll 8
        for (int kc = 0; kc < HDIM / 4; kc++) {
            ulonglong2 W0 = *(const ulonglong2*)(wev + kc * 256);          // even col
            ulonglong2 W1 = *(const ulonglong2*)(wev + kc * 256 + 128);    // odd col
            ull h00 = hq0[kc * 2], h01 = hq0[kc * 2 + 1];
            ull h10 = hq1[kc * 2], h11 = hq1[kc * 2 + 1];
            ffma2(a000, h00, W0.x); ffma2(a001, h01, W0.y);
            ffma2(a010, h00, W1.x); ffma2(a011, h01, W1.y);
            ffma2(a100, h10, W0.x); ffma2(a101, h11, W0.y);
            ffma2(a110, h10, W1.x); ffma2(a111, h11, W1.y);
        }
        {
            float2 p; float s00, s01, s10, s11;
            p = unpack2(a000); s00 = p.x + p.y; p = unpack2(a001); s00 += p.x + p.y;
            p = unpack2(a010); s01 = p.x + p.y; p = unpack2(a011); s01 += p.x + p.y;
            p = unpack2(a100); s10 = p.x + p.y; p = unpack2(a101); s10 += p.x + p.y;
            p = unpack2(a110); s11 = p.x + p.y; p = unpack2(a111); s11 += p.x + p.y;
            gs[lb0 * GSP + lc0] = s00 + xv00; gs[lb0 * GSP + lc1] = s01 + xv01;
            gs[lb1 * GSP + lc0] = s10 + xv10; gs[lb1 * GSP + lc1] = s11 + xv11;
        }
        __syncthreads();

        // ---- cell update ----
        {
            float gi = gs[ub * GSP + 0 + uj],  gf = gs[ub * GSP + 16 + uj];
            float gg = gs[ub * GSP + 32 + uj], go = gs[ub * GSP + 48 + uj];
            float i_ = sigf(gi), f_ = sigf(gf), gv = tanhf(gg), o_ = sigf(go);
            cstate = fmaf(f_, cstate, i_ * gv);
            float h = o_ * tanhf(cstate);
            __stcg(hdst, h);
            if (t == SEQ - 1)
                g_last[(bg * 16 + ub) * (2 * HDIM) + jg * 16 + uj] = h;
        }

        if (t < SEQ - 1) {
            const size_t off = tstride * (size_t)(t + 1);
            xv00 = __ldcs(xp00 + off); xv01 = __ldcs(xp01 + off);
            xv10 = __ldcs(xp10 + off); xv11 = __ldcs(xp11 + off);
            FLAGBAR(t + 1);
        }
    }
}

// ================================================================
// Kernel 3b: reset barrier flags so the next launch/replay starts
// from zero (stream-ordered after the scan).
// ================================================================
__global__ void reset_flags_kernel()
{
    if (threadIdx.x < 128) g_flags[threadIdx.x][0] = 0ull;
}

// ================================================================
// Kernel 4: final FC. 64 blocks x 512 threads, 4 threads/output.
// ================================================================
__global__ void __launch_bounds__(512) fc_kernel(
    const float* __restrict__ Wfc, const float* __restrict__ bfc,
    float* __restrict__ out)
{
    __shared__ float ls[2 * HDIM];
    const int b = blockIdx.x, tid = threadIdx.x;
    if (tid < 256)
        ((float4*)ls)[tid] = ((const float4*)(g_last + (size_t)b * 2 * HDIM))[tid];
    __syncthreads();

    const int o = tid >> 2, q = tid & 3;
    const float4* wp = (const float4*)(Wfc + (size_t)o * (2 * HDIM)) + q * 64;
    const float4* lv = (const float4*)ls + q * 64;
    float acc = 0.f;
#pragma unroll 16
    for (int k = 0; k < 64; k++) {
        float4 w = __ldg(wp + k);
        float4 l = lv[k];
        acc += w.x * l.x + w.y * l.y + w.z * l.z + w.w * l.w;
    }
    acc += __shfl_xor_sync(0xffffffff, acc, 1);
    acc += __shfl_xor_sync(0xffffffff, acc, 2);
    if (q == 0) out[b * ODIM + o] = acc + bfc[o];
}

// ================================================================
extern "C" void kernel_launch(void* const* d_in, const int* in_sizes, int n_in,
                              void* d_out, int out_size)
{
    const float* x      = (const float*)d_in[0];
    const float* W_ih_f = (const float*)d_in[1];
    const float* W_hh_f = (const float*)d_in[2];
    const float* b_f    = (const float*)d_in[3];
    const float* W_ih_b = (const float*)d_in[4];
    const float* b_b    = (const float*)d_in[6];
    const float* W_fc   = (const float*)d_in[7];
    const float* b_fc   = (const float*)d_in[8];
    float* out = (float*)d_out;

    cudaFuncSetAttribute(gemm_xp_kernel,
                         cudaFuncAttributeMaxDynamicSharedMemorySize, GEMM_SMEM);
    cudaFuncSetAttribute(lstm_scan_kernel,
                         cudaFuncAttributeMaxDynamicSharedMemorySize, SCAN_SMEM);

    gemm_xp_kernel<<<dim3(G4 / BN, SEQ / 2), 256, GEMM_SMEM>>>(x, W_ih_f, b_f);
    bwd_last_kernel<<<dim3(BATCH, 2), 256>>>(x, W_ih_b, b_b);
    lstm_scan_kernel<<<SCAN_BLOCKS, 256, SCAN_SMEM>>>(W_hh_f);
    reset_flags_kernel<<<1, 128>>>();
    fc_kernel<<<BATCH, 512>>>(W_fc, b_fc, out);
}